// round 12
// baseline (speedup 1.0000x reference)
#include <cuda_runtime.h>
#include <cuda_bf16.h>
#include <cuda_fp16.h>
#include <cstdint>

#define NN 50000
#define EE 800000
#define DD 96
#define DD4 24
#define NPAD 53248          // 13 tiles * 4096, padded for int4 scan

// scratch (zero-initialized at load; g_count kept zeroed call-to-call by spmm)
__device__ __half g_support_h[(size_t)NN * DD];  // X @ W in fp16 (9.6 MB)
__device__ int   g_count[NPAD];                  // histogram -> write-ptr (in place)
__device__ int   g_rowptr[NN + 1];
__device__ int2  g_edge[EE];                     // sorted (col, val_bits)

// ---- f32x2 helpers -------------------------------------------------------
__device__ __forceinline__ void fma2(unsigned long long& d,
                                     unsigned long long a,
                                     unsigned long long b) {
    asm("fma.rn.f32x2 %0, %1, %2, %0;" : "+l"(d) : "l"(a), "l"(b));
}
__device__ __forceinline__ unsigned long long pack2(float lo, float hi) {
    unsigned long long r;
    asm("mov.b64 %0, {%1, %2};" : "=l"(r) : "f"(lo), "f"(hi));
    return r;
}
__device__ __forceinline__ unsigned h2u(__half2 h) {
    return *reinterpret_cast<unsigned*>(&h);
}

// ---------------------------------------------------------------------------
// GEMM: support[N,96] = X[N,96] @ W[96,96], f32x2 packed FMA, fp16 store.
// Tail: fused row histogram (g_count zero on entry), scalar grid-stride REDs.
// ---------------------------------------------------------------------------
__global__ __launch_bounds__(96) void gemm_kernel(const float* __restrict__ x,
                                                  const float* __restrict__ w,
                                                  const int* __restrict__ erow) {
    __shared__ float Ws[DD * DD];      // [k][col]
    __shared__ float Xt[DD * 32];      // [k][row]

    const int tid = threadIdx.x;       // 0..95
    const int row0 = blockIdx.x * 32;

    {
        const float4* w4 = reinterpret_cast<const float4*>(w);
        float4* ws4 = reinterpret_cast<float4*>(Ws);
#pragma unroll
        for (int i = 0; i < 24; i++) ws4[tid + i * 96] = w4[tid + i * 96];
    }
    {
        const int r = tid & 31;
        const int wp = tid >> 5;
        const int gr = row0 + r;
        const float4* x4 = reinterpret_cast<const float4*>(x);
#pragma unroll
        for (int i = 0; i < 8; i++) {
            int k4 = wp + 3 * i;
            float4 v = make_float4(0.f, 0.f, 0.f, 0.f);
            if (gr < NN) v = x4[(size_t)gr * DD4 + k4];
            Xt[(k4 * 4 + 0) * 32 + r] = v.x;
            Xt[(k4 * 4 + 1) * 32 + r] = v.y;
            Xt[(k4 * 4 + 2) * 32 + r] = v.z;
            Xt[(k4 * 4 + 3) * 32 + r] = v.w;
        }
    }
    __syncthreads();

    const int rt = tid / DD4;
    const int ct = tid % DD4;

    unsigned long long acc[4][4];
#pragma unroll
    for (int i = 0; i < 4; i++)
#pragma unroll
        for (int j = 0; j < 4; j++) acc[i][j] = 0ull;

    const float4* ws4 = reinterpret_cast<const float4*>(Ws);
#pragma unroll 4
    for (int k = 0; k < DD; k++) {
        const double* xp = reinterpret_cast<const double*>(Xt + k * 32 + rt * 8);
        unsigned long long x0 = __double_as_longlong(xp[0]);
        unsigned long long x1 = __double_as_longlong(xp[1]);
        unsigned long long x2 = __double_as_longlong(xp[2]);
        unsigned long long x3 = __double_as_longlong(xp[3]);
        float4 wv = ws4[k * DD4 + ct];
        unsigned long long w0 = pack2(wv.x, wv.x);
        unsigned long long w1 = pack2(wv.y, wv.y);
        unsigned long long w2 = pack2(wv.z, wv.z);
        unsigned long long w3 = pack2(wv.w, wv.w);
        fma2(acc[0][0], x0, w0); fma2(acc[0][1], x0, w1); fma2(acc[0][2], x0, w2); fma2(acc[0][3], x0, w3);
        fma2(acc[1][0], x1, w0); fma2(acc[1][1], x1, w1); fma2(acc[1][2], x1, w2); fma2(acc[1][3], x1, w3);
        fma2(acc[2][0], x2, w0); fma2(acc[2][1], x2, w1); fma2(acc[2][2], x2, w2); fma2(acc[2][3], x2, w3);
        fma2(acc[3][0], x3, w0); fma2(acc[3][1], x3, w1); fma2(acc[3][2], x3, w2); fma2(acc[3][3], x3, w3);
    }

    uint2* s2 = reinterpret_cast<uint2*>(g_support_h);
#pragma unroll
    for (int i = 0; i < 4; i++) {
        int grl = row0 + rt * 8 + 2 * i;
        float l0 = __uint_as_float((unsigned)(acc[i][0]));
        float l1 = __uint_as_float((unsigned)(acc[i][1]));
        float l2 = __uint_as_float((unsigned)(acc[i][2]));
        float l3 = __uint_as_float((unsigned)(acc[i][3]));
        float h0 = __uint_as_float((unsigned)(acc[i][0] >> 32));
        float h1 = __uint_as_float((unsigned)(acc[i][1] >> 32));
        float h2 = __uint_as_float((unsigned)(acc[i][2] >> 32));
        float h3 = __uint_as_float((unsigned)(acc[i][3] >> 32));
        uint2 lo, hi;
        lo.x = h2u(__floats2half2_rn(l0, l1));
        lo.y = h2u(__floats2half2_rn(l2, l3));
        hi.x = h2u(__floats2half2_rn(h0, h1));
        hi.y = h2u(__floats2half2_rn(h2, h3));
        if (grl < NN)     s2[(size_t)grl * DD4 + ct] = lo;
        if (grl + 1 < NN) s2[(size_t)(grl + 1) * DD4 + ct] = hi;
    }

    // ---- fused histogram tail (scalar fire-and-forget REDs) ----
    {
        const int T = gridDim.x * 96;              // 150048
        for (int e = blockIdx.x * 96 + tid; e < EE; e += T)
            atomicAdd(&g_count[erow[e]], 1);
    }
}

// ---------------------------------------------------------------------------
// Single-block exclusive scan over g_count[0..NPAD) -> g_rowptr.
// Leaves g_count[i] = rowptr[i] in place (write pointers for build).
// ---------------------------------------------------------------------------
__global__ __launch_bounds__(1024) void scan_kernel() {
    __shared__ int warpsum[32];
    __shared__ int blocktot;

    const int t = threadIdx.x;
    const int lane = t & 31;
    const int wid = t >> 5;

    if (t == 0) g_rowptr[NN] = EE;

    int carry = 0;
    const int4* c4 = reinterpret_cast<const int4*>(g_count);

#pragma unroll
    for (int tile = 0; tile < 13; tile++) {
        int idx4 = tile * 1024 + t;
        int4 v = c4[idx4];
        int s = v.x + v.y + v.z + v.w;

        int inc = s;
#pragma unroll
        for (int off = 1; off < 32; off <<= 1) {
            int n = __shfl_up_sync(0xffffffffu, inc, off);
            if (lane >= off) inc += n;
        }
        if (lane == 31) warpsum[wid] = inc;
        __syncthreads();

        if (wid == 0) {
            int ws = warpsum[lane];
            int winc = ws;
#pragma unroll
            for (int off = 1; off < 32; off <<= 1) {
                int n = __shfl_up_sync(0xffffffffu, winc, off);
                if (lane >= off) winc += n;
            }
            warpsum[lane] = winc - ws;
            if (lane == 31) blocktot = winc;
        }
        __syncthreads();

        int base = carry + warpsum[wid] + (inc - s);
        int i0 = idx4 * 4;
        if (i0 < NN) {
            int4 o;
            o.x = base;
            o.y = base + v.x;
            o.z = o.y + v.y;
            o.w = o.z + v.z;
            reinterpret_cast<int4*>(g_rowptr)[idx4] = o;
            reinterpret_cast<int4*>(g_count)[idx4] = o;   // same-thread rewrite
        }
        carry += blocktot;
        __syncthreads();
    }
}

// ---------------------------------------------------------------------------
// Bucket-place edges, 4 per thread (4 independent ATOMGs in flight).
// ---------------------------------------------------------------------------
__global__ __launch_bounds__(256) void build_kernel(const int* __restrict__ erow,
                                                    const int* __restrict__ ecol,
                                                    const float* __restrict__ eval_) {
    int t = blockIdx.x * 256 + threadIdx.x;
    if (t >= EE / 4) return;
    int4   r = reinterpret_cast<const int4*>(erow)[t];
    int4   c = reinterpret_cast<const int4*>(ecol)[t];
    float4 v = reinterpret_cast<const float4*>(eval_)[t];
    int p0 = atomicAdd(&g_count[r.x], 1);
    int p1 = atomicAdd(&g_count[r.y], 1);
    int p2 = atomicAdd(&g_count[r.z], 1);
    int p3 = atomicAdd(&g_count[r.w], 1);
    g_edge[p0] = make_int2(c.x, __float_as_int(v.x));
    g_edge[p1] = make_int2(c.y, __float_as_int(v.y));
    g_edge[p2] = make_int2(c.z, __float_as_int(v.z));
    g_edge[p3] = make_int2(c.w, __float_as_int(v.w));
}

// ---------------------------------------------------------------------------
// SpMM: 8 lanes per row (warp = 4 rows). Lane owns 12 features:
// 6 f32x2 accumulators, 3x uint2 fp16 gathers per edge. Low regs -> high occ.
// Bias fused, 3x STG.128 per lane. Side job: re-zero g_count.
// ---------------------------------------------------------------------------
__global__ __launch_bounds__(256) void spmm_kernel(const float* __restrict__ b,
                                                   float* __restrict__ out) {
    // re-zero counters for next call (grid 1563 blocks covers NPAD)
    {
        int zi = blockIdx.x * 256 + threadIdx.x;
        if (zi < NPAD) g_count[zi] = 0;
    }

    const int lane = threadIdx.x & 31;
    const int g    = lane >> 3;          // group 0..3
    const int sub  = lane & 7;           // 0..7
    const int row  = blockIdx.x * 32 + (threadIdx.x >> 5) * 4 + g;
    if (row >= NN) return;

    const int start = g_rowptr[row];
    const int end   = g_rowptr[row + 1];

    // 12 fp32 features as 6 packed f32x2 accumulators
    unsigned long long acc[6];
#pragma unroll
    for (int i = 0; i < 6; i++) acc[i] = 0ull;

    const uint2* s2 = reinterpret_cast<const uint2*>(g_support_h);  // 24 uint2/row

    for (int e = start; e < end; e++) {
        int2 ev = g_edge[e];                       // 8 lanes same addr: broadcast
        size_t base = (size_t)ev.x * 24 + sub * 3;
        uint2 u0 = s2[base + 0];
        uint2 u1 = s2[base + 1];
        uint2 u2 = s2[base + 2];
        float vi = __int_as_float(ev.y);
        unsigned long long vv = pack2(vi, vi);
        float2 f;
        f = __half22float2(*reinterpret_cast<const __half2*>(&u0.x)); fma2(acc[0], pack2(f.x, f.y), vv);
        f = __half22float2(*reinterpret_cast<const __half2*>(&u0.y)); fma2(acc[1], pack2(f.x, f.y), vv);
        f = __half22float2(*reinterpret_cast<const __half2*>(&u1.x)); fma2(acc[2], pack2(f.x, f.y), vv);
        f = __half22float2(*reinterpret_cast<const __half2*>(&u1.y)); fma2(acc[3], pack2(f.x, f.y), vv);
        f = __half22float2(*reinterpret_cast<const __half2*>(&u2.x)); fma2(acc[4], pack2(f.x, f.y), vv);
        f = __half22float2(*reinterpret_cast<const __half2*>(&u2.y)); fma2(acc[5], pack2(f.x, f.y), vv);
    }

    // write 12 features = 3 float4 at out[row*96 + sub*12], bias fused
    const float4* b4 = reinterpret_cast<const float4*>(b);
    float4* o4 = reinterpret_cast<float4*>(out) + (size_t)row * DD4 + sub * 3;
#pragma unroll
    for (int q = 0; q < 3; q++) {
        float4 bb = b4[sub * 3 + q];
        float4 r;
        r.x = __uint_as_float((unsigned)(acc[q * 2 + 0]))         + bb.x;
        r.y = __uint_as_float((unsigned)(acc[q * 2 + 0] >> 32))   + bb.y;
        r.z = __uint_as_float((unsigned)(acc[q * 2 + 1]))         + bb.z;
        r.w = __uint_as_float((unsigned)(acc[q * 2 + 1] >> 32))   + bb.w;
        o4[q] = r;
    }
}

extern "C" void kernel_launch(void* const* d_in, const int* in_sizes, int n_in,
                              void* d_out, int out_size) {
    const float* x     = (const float*)d_in[0];
    const int*   erow  = (const int*)d_in[1];
    const int*   ecol  = (const int*)d_in[2];
    const float* evalv = (const float*)d_in[3];
    const float* w     = (const float*)d_in[4];
    const float* b     = (const float*)d_in[5];
    float* out = (float*)d_out;

    gemm_kernel<<<(NN + 31) / 32, 96>>>(x, w, erow);       // + fused histogram
    scan_kernel<<<1, 1024>>>();
    build_kernel<<<(EE / 4 + 255) / 256, 256>>>(erow, ecol, evalv);
    spmm_kernel<<<(NN + 31) / 32, 256>>>(b, out);          // + re-zero counters
}

// round 13
// speedup vs baseline: 1.2193x; 1.2193x over previous
#include <cuda_runtime.h>
#include <cuda_bf16.h>
#include <cuda_fp16.h>
#include <cstdint>

#define NN 50000
#define EE 800000
#define DD 96
#define DD4 24
#define NPAD 53248          // 13 tiles * 4096, padded for int4 scan

// scratch (zero-initialized at load; g_count kept zeroed call-to-call by spmm)
__device__ __half g_support_h[(size_t)NN * DD];  // X @ W in fp16 (9.6 MB)
__device__ int   g_count[NPAD];                  // histogram -> write-ptr (in place)
__device__ int   g_rowptr[NN + 1];
__device__ int2  g_edge[EE];                     // sorted (col, val_bits)

// ---- f32x2 helpers -------------------------------------------------------
__device__ __forceinline__ void fma2(unsigned long long& d,
                                     unsigned long long a,
                                     unsigned long long b) {
    asm("fma.rn.f32x2 %0, %1, %2, %0;" : "+l"(d) : "l"(a), "l"(b));
}
__device__ __forceinline__ unsigned long long pack2(float lo, float hi) {
    unsigned long long r;
    asm("mov.b64 %0, {%1, %2};" : "=l"(r) : "f"(lo), "f"(hi));
    return r;
}
__device__ __forceinline__ unsigned h2u(__half2 h) {
    return *reinterpret_cast<unsigned*>(&h);
}

// ---------------------------------------------------------------------------
// GEMM: support[N,96] = X[N,96] @ W[96,96], f32x2 packed FMA, fp16 store.
// Tail: fused row histogram (g_count zero on entry), scalar grid-stride REDs.
// ---------------------------------------------------------------------------
__global__ __launch_bounds__(96) void gemm_kernel(const float* __restrict__ x,
                                                  const float* __restrict__ w,
                                                  const int* __restrict__ erow) {
    __shared__ float Ws[DD * DD];      // [k][col]
    __shared__ float Xt[DD * 32];      // [k][row]

    const int tid = threadIdx.x;       // 0..95
    const int row0 = blockIdx.x * 32;

    {
        const float4* w4 = reinterpret_cast<const float4*>(w);
        float4* ws4 = reinterpret_cast<float4*>(Ws);
#pragma unroll
        for (int i = 0; i < 24; i++) ws4[tid + i * 96] = w4[tid + i * 96];
    }
    {
        const int r = tid & 31;
        const int wp = tid >> 5;
        const int gr = row0 + r;
        const float4* x4 = reinterpret_cast<const float4*>(x);
#pragma unroll
        for (int i = 0; i < 8; i++) {
            int k4 = wp + 3 * i;
            float4 v = make_float4(0.f, 0.f, 0.f, 0.f);
            if (gr < NN) v = x4[(size_t)gr * DD4 + k4];
            Xt[(k4 * 4 + 0) * 32 + r] = v.x;
            Xt[(k4 * 4 + 1) * 32 + r] = v.y;
            Xt[(k4 * 4 + 2) * 32 + r] = v.z;
            Xt[(k4 * 4 + 3) * 32 + r] = v.w;
        }
    }
    __syncthreads();

    const int rt = tid / DD4;
    const int ct = tid % DD4;

    unsigned long long acc[4][4];
#pragma unroll
    for (int i = 0; i < 4; i++)
#pragma unroll
        for (int j = 0; j < 4; j++) acc[i][j] = 0ull;

    const float4* ws4 = reinterpret_cast<const float4*>(Ws);
#pragma unroll 4
    for (int k = 0; k < DD; k++) {
        const double* xp = reinterpret_cast<const double*>(Xt + k * 32 + rt * 8);
        unsigned long long x0 = __double_as_longlong(xp[0]);
        unsigned long long x1 = __double_as_longlong(xp[1]);
        unsigned long long x2 = __double_as_longlong(xp[2]);
        unsigned long long x3 = __double_as_longlong(xp[3]);
        float4 wv = ws4[k * DD4 + ct];
        unsigned long long w0 = pack2(wv.x, wv.x);
        unsigned long long w1 = pack2(wv.y, wv.y);
        unsigned long long w2 = pack2(wv.z, wv.z);
        unsigned long long w3 = pack2(wv.w, wv.w);
        fma2(acc[0][0], x0, w0); fma2(acc[0][1], x0, w1); fma2(acc[0][2], x0, w2); fma2(acc[0][3], x0, w3);
        fma2(acc[1][0], x1, w0); fma2(acc[1][1], x1, w1); fma2(acc[1][2], x1, w2); fma2(acc[1][3], x1, w3);
        fma2(acc[2][0], x2, w0); fma2(acc[2][1], x2, w1); fma2(acc[2][2], x2, w2); fma2(acc[2][3], x2, w3);
        fma2(acc[3][0], x3, w0); fma2(acc[3][1], x3, w1); fma2(acc[3][2], x3, w2); fma2(acc[3][3], x3, w3);
    }

    uint2* s2 = reinterpret_cast<uint2*>(g_support_h);
#pragma unroll
    for (int i = 0; i < 4; i++) {
        int grl = row0 + rt * 8 + 2 * i;
        float l0 = __uint_as_float((unsigned)(acc[i][0]));
        float l1 = __uint_as_float((unsigned)(acc[i][1]));
        float l2 = __uint_as_float((unsigned)(acc[i][2]));
        float l3 = __uint_as_float((unsigned)(acc[i][3]));
        float h0 = __uint_as_float((unsigned)(acc[i][0] >> 32));
        float h1 = __uint_as_float((unsigned)(acc[i][1] >> 32));
        float h2 = __uint_as_float((unsigned)(acc[i][2] >> 32));
        float h3 = __uint_as_float((unsigned)(acc[i][3] >> 32));
        uint2 lo, hi;
        lo.x = h2u(__floats2half2_rn(l0, l1));
        lo.y = h2u(__floats2half2_rn(l2, l3));
        hi.x = h2u(__floats2half2_rn(h0, h1));
        hi.y = h2u(__floats2half2_rn(h2, h3));
        if (grl < NN)     s2[(size_t)grl * DD4 + ct] = lo;
        if (grl + 1 < NN) s2[(size_t)(grl + 1) * DD4 + ct] = hi;
    }

    // ---- fused histogram tail (scalar fire-and-forget REDs) ----
    {
        const int T = gridDim.x * 96;              // 150048
        for (int e = blockIdx.x * 96 + tid; e < EE; e += T)
            atomicAdd(&g_count[erow[e]], 1);
    }
}

// ---------------------------------------------------------------------------
// Single-block exclusive scan over g_count[0..NPAD) -> g_rowptr.
// Leaves g_count[i] = rowptr[i] in place (write pointers for build).
// ---------------------------------------------------------------------------
__global__ __launch_bounds__(1024) void scan_kernel() {
    __shared__ int warpsum[32];
    __shared__ int blocktot;

    const int t = threadIdx.x;
    const int lane = t & 31;
    const int wid = t >> 5;

    if (t == 0) g_rowptr[NN] = EE;

    int carry = 0;
    const int4* c4 = reinterpret_cast<const int4*>(g_count);

#pragma unroll
    for (int tile = 0; tile < 13; tile++) {
        int idx4 = tile * 1024 + t;
        int4 v = c4[idx4];
        int s = v.x + v.y + v.z + v.w;

        int inc = s;
#pragma unroll
        for (int off = 1; off < 32; off <<= 1) {
            int n = __shfl_up_sync(0xffffffffu, inc, off);
            if (lane >= off) inc += n;
        }
        if (lane == 31) warpsum[wid] = inc;
        __syncthreads();

        if (wid == 0) {
            int ws = warpsum[lane];
            int winc = ws;
#pragma unroll
            for (int off = 1; off < 32; off <<= 1) {
                int n = __shfl_up_sync(0xffffffffu, winc, off);
                if (lane >= off) winc += n;
            }
            warpsum[lane] = winc - ws;
            if (lane == 31) blocktot = winc;
        }
        __syncthreads();

        int base = carry + warpsum[wid] + (inc - s);
        int i0 = idx4 * 4;
        if (i0 < NN) {
            int4 o;
            o.x = base;
            o.y = base + v.x;
            o.z = o.y + v.y;
            o.w = o.z + v.z;
            reinterpret_cast<int4*>(g_rowptr)[idx4] = o;
            reinterpret_cast<int4*>(g_count)[idx4] = o;   // same-thread rewrite
        }
        carry += blocktot;
        __syncthreads();
    }
}

// ---------------------------------------------------------------------------
// Bucket-place edges, 4 per thread (4 independent ATOMGs in flight).
// ---------------------------------------------------------------------------
__global__ __launch_bounds__(256) void build_kernel(const int* __restrict__ erow,
                                                    const int* __restrict__ ecol,
                                                    const float* __restrict__ eval_) {
    int t = blockIdx.x * 256 + threadIdx.x;
    if (t >= EE / 4) return;
    int4   r = reinterpret_cast<const int4*>(erow)[t];
    int4   c = reinterpret_cast<const int4*>(ecol)[t];
    float4 v = reinterpret_cast<const float4*>(eval_)[t];
    int p0 = atomicAdd(&g_count[r.x], 1);
    int p1 = atomicAdd(&g_count[r.y], 1);
    int p2 = atomicAdd(&g_count[r.z], 1);
    int p3 = atomicAdd(&g_count[r.w], 1);
    g_edge[p0] = make_int2(c.x, __float_as_int(v.x));
    g_edge[p1] = make_int2(c.y, __float_as_int(v.y));
    g_edge[p2] = make_int2(c.z, __float_as_int(v.z));
    g_edge[p3] = make_int2(c.w, __float_as_int(v.w));
}

// ---------------------------------------------------------------------------
// SpMM: block-per-row, feature-parallel. 96 threads = 1 row.
// Thread t: edge-slot half = t/48, feature pair sub = t%48.
// 2 edges consumed per step; gathers are coalesced half2 (128B wavefronts).
// Edge records staged in smem. Bias fused. Side job: re-zero g_count.
// ---------------------------------------------------------------------------
__global__ __launch_bounds__(96) void spmm_kernel(const float* __restrict__ b,
                                                  float* __restrict__ out) {
    __shared__ int2  se[96];
    __shared__ float2 red[48];

    const int row = blockIdx.x;
    const int tid = threadIdx.x;

    // re-zero counters for next call (first 555 blocks cover NPAD)
    {
        int zi = row * 96 + tid;
        if (zi < NPAD) g_count[zi] = 0;
    }

    const int half = tid / 48;     // which edge of the pair
    const int sub  = tid % 48;     // feature pair index

    const int start = g_rowptr[row];
    const int end   = g_rowptr[row + 1];

    float2 acc = make_float2(0.f, 0.f);
    const __half2* sh2 = reinterpret_cast<const __half2*>(g_support_h);  // 48 per row

    for (int base = start; base < end; base += 96) {
        int n = min(96, end - base);
        __syncthreads();                    // protect se reuse across chunks
        if (tid < n) se[tid] = g_edge[base + tid];
        __syncthreads();

        for (int i = 0; i < n; i += 2) {
            int ei = i + half;
            if (ei < n) {
                int2 ev = se[ei];
                float vi = __int_as_float(ev.y);
                __half2 h = sh2[(size_t)ev.x * 48 + sub];
                float2 f = __half22float2(h);
                acc.x += vi * f.x;
                acc.y += vi * f.y;
            }
        }
    }

    // combine the two edge-slots: half=1 -> smem, half=0 adds and writes
    if (half == 1) red[sub] = acc;
    __syncthreads();
    if (half == 0) {
        float2 o = red[sub];
        float2 bb = reinterpret_cast<const float2*>(b)[sub];
        float2 r;
        r.x = acc.x + o.x + bb.x;
        r.y = acc.y + o.y + bb.y;
        reinterpret_cast<float2*>(out)[(size_t)row * 48 + sub] = r;
    }
}

extern "C" void kernel_launch(void* const* d_in, const int* in_sizes, int n_in,
                              void* d_out, int out_size) {
    const float* x     = (const float*)d_in[0];
    const int*   erow  = (const int*)d_in[1];
    const int*   ecol  = (const int*)d_in[2];
    const float* evalv = (const float*)d_in[3];
    const float* w     = (const float*)d_in[4];
    const float* b     = (const float*)d_in[5];
    float* out = (float*)d_out;

    gemm_kernel<<<(NN + 31) / 32, 96>>>(x, w, erow);       // + fused histogram
    scan_kernel<<<1, 1024>>>();
    build_kernel<<<(EE / 4 + 255) / 256, 256>>>(erow, ecol, evalv);
    spmm_kernel<<<NN, 96>>>(b, out);                       // + re-zero counters
}

// round 14
// speedup vs baseline: 1.4296x; 1.1725x over previous
#include <cuda_runtime.h>
#include <cuda_bf16.h>
#include <cuda_fp16.h>
#include <cstdint>

#define NN 50000
#define EE 800000
#define DD 96
#define DD4 24
#define NPAD 53248          // 13 tiles * 4096, padded for int4 scan

// scratch (zero-initialized at load; g_count kept zeroed call-to-call by spmm)
__device__ __half g_support_h[(size_t)NN * DD];  // X @ W in fp16 (9.6 MB)
__device__ int   g_count[NPAD];                  // histogram -> write-ptr (in place)
__device__ int   g_rowptr[NN + 1];
__device__ int2  g_edge[EE];                     // sorted (col, val_bits)

// ---- f32x2 helpers -------------------------------------------------------
__device__ __forceinline__ void fma2(unsigned long long& d,
                                     unsigned long long a,
                                     unsigned long long b) {
    asm("fma.rn.f32x2 %0, %1, %2, %0;" : "+l"(d) : "l"(a), "l"(b));
}
__device__ __forceinline__ unsigned long long pack2(float lo, float hi) {
    unsigned long long r;
    asm("mov.b64 %0, {%1, %2};" : "=l"(r) : "f"(lo), "f"(hi));
    return r;
}
__device__ __forceinline__ unsigned h2u(__half2 h) {
    return *reinterpret_cast<unsigned*>(&h);
}

// ---------------------------------------------------------------------------
// GEMM: support[N,96] = X[N,96] @ W[96,96], f32x2 packed FMA, fp16 store.
// (histogram un-fused: it runs concurrently on a second stream)
// ---------------------------------------------------------------------------
__global__ __launch_bounds__(96) void gemm_kernel(const float* __restrict__ x,
                                                  const float* __restrict__ w) {
    __shared__ float Ws[DD * DD];      // [k][col]
    __shared__ float Xt[DD * 32];      // [k][row]

    const int tid = threadIdx.x;       // 0..95
    const int row0 = blockIdx.x * 32;

    {
        const float4* w4 = reinterpret_cast<const float4*>(w);
        float4* ws4 = reinterpret_cast<float4*>(Ws);
#pragma unroll
        for (int i = 0; i < 24; i++) ws4[tid + i * 96] = w4[tid + i * 96];
    }
    {
        const int r = tid & 31;
        const int wp = tid >> 5;
        const int gr = row0 + r;
        const float4* x4 = reinterpret_cast<const float4*>(x);
#pragma unroll
        for (int i = 0; i < 8; i++) {
            int k4 = wp + 3 * i;
            float4 v = make_float4(0.f, 0.f, 0.f, 0.f);
            if (gr < NN) v = x4[(size_t)gr * DD4 + k4];
            Xt[(k4 * 4 + 0) * 32 + r] = v.x;
            Xt[(k4 * 4 + 1) * 32 + r] = v.y;
            Xt[(k4 * 4 + 2) * 32 + r] = v.z;
            Xt[(k4 * 4 + 3) * 32 + r] = v.w;
        }
    }
    __syncthreads();

    const int rt = tid / DD4;
    const int ct = tid % DD4;

    unsigned long long acc[4][4];
#pragma unroll
    for (int i = 0; i < 4; i++)
#pragma unroll
        for (int j = 0; j < 4; j++) acc[i][j] = 0ull;

    const float4* ws4 = reinterpret_cast<const float4*>(Ws);
#pragma unroll 4
    for (int k = 0; k < DD; k++) {
        const double* xp = reinterpret_cast<const double*>(Xt + k * 32 + rt * 8);
        unsigned long long x0 = __double_as_longlong(xp[0]);
        unsigned long long x1 = __double_as_longlong(xp[1]);
        unsigned long long x2 = __double_as_longlong(xp[2]);
        unsigned long long x3 = __double_as_longlong(xp[3]);
        float4 wv = ws4[k * DD4 + ct];
        unsigned long long w0 = pack2(wv.x, wv.x);
        unsigned long long w1 = pack2(wv.y, wv.y);
        unsigned long long w2 = pack2(wv.z, wv.z);
        unsigned long long w3 = pack2(wv.w, wv.w);
        fma2(acc[0][0], x0, w0); fma2(acc[0][1], x0, w1); fma2(acc[0][2], x0, w2); fma2(acc[0][3], x0, w3);
        fma2(acc[1][0], x1, w0); fma2(acc[1][1], x1, w1); fma2(acc[1][2], x1, w2); fma2(acc[1][3], x1, w3);
        fma2(acc[2][0], x2, w0); fma2(acc[2][1], x2, w1); fma2(acc[2][2], x2, w2); fma2(acc[2][3], x2, w3);
        fma2(acc[3][0], x3, w0); fma2(acc[3][1], x3, w1); fma2(acc[3][2], x3, w2); fma2(acc[3][3], x3, w3);
    }

    uint2* s2 = reinterpret_cast<uint2*>(g_support_h);
#pragma unroll
    for (int i = 0; i < 4; i++) {
        int grl = row0 + rt * 8 + 2 * i;
        float l0 = __uint_as_float((unsigned)(acc[i][0]));
        float l1 = __uint_as_float((unsigned)(acc[i][1]));
        float l2 = __uint_as_float((unsigned)(acc[i][2]));
        float l3 = __uint_as_float((unsigned)(acc[i][3]));
        float h0 = __uint_as_float((unsigned)(acc[i][0] >> 32));
        float h1 = __uint_as_float((unsigned)(acc[i][1] >> 32));
        float h2 = __uint_as_float((unsigned)(acc[i][2] >> 32));
        float h3 = __uint_as_float((unsigned)(acc[i][3] >> 32));
        uint2 lo, hi;
        lo.x = h2u(__floats2half2_rn(l0, l1));
        lo.y = h2u(__floats2half2_rn(l2, l3));
        hi.x = h2u(__floats2half2_rn(h0, h1));
        hi.y = h2u(__floats2half2_rn(h2, h3));
        if (grl < NN)     s2[(size_t)grl * DD4 + ct] = lo;
        if (grl + 1 < NN) s2[(size_t)(grl + 1) * DD4 + ct] = hi;
    }
}

// ---------------------------------------------------------------------------
// Histogram of edge rows (fire-and-forget REDs), standalone on stream 1.
// ---------------------------------------------------------------------------
__global__ void hist_kernel(const int* __restrict__ erow) {
    int e = blockIdx.x * 256 + threadIdx.x;
    if (e < EE) atomicAdd(&g_count[erow[e]], 1);
}

// ---------------------------------------------------------------------------
// Single-block exclusive scan over g_count[0..NPAD) -> g_rowptr.
// Leaves g_count[i] = rowptr[i] in place (write pointers for build).
// ---------------------------------------------------------------------------
__global__ __launch_bounds__(1024) void scan_kernel() {
    __shared__ int warpsum[32];
    __shared__ int blocktot;

    const int t = threadIdx.x;
    const int lane = t & 31;
    const int wid = t >> 5;

    if (t == 0) g_rowptr[NN] = EE;

    int carry = 0;
    const int4* c4 = reinterpret_cast<const int4*>(g_count);

#pragma unroll
    for (int tile = 0; tile < 13; tile++) {
        int idx4 = tile * 1024 + t;
        int4 v = c4[idx4];
        int s = v.x + v.y + v.z + v.w;

        int inc = s;
#pragma unroll
        for (int off = 1; off < 32; off <<= 1) {
            int n = __shfl_up_sync(0xffffffffu, inc, off);
            if (lane >= off) inc += n;
        }
        if (lane == 31) warpsum[wid] = inc;
        __syncthreads();

        if (wid == 0) {
            int ws = warpsum[lane];
            int winc = ws;
#pragma unroll
            for (int off = 1; off < 32; off <<= 1) {
                int n = __shfl_up_sync(0xffffffffu, winc, off);
                if (lane >= off) winc += n;
            }
            warpsum[lane] = winc - ws;
            if (lane == 31) blocktot = winc;
        }
        __syncthreads();

        int base = carry + warpsum[wid] + (inc - s);
        int i0 = idx4 * 4;
        if (i0 < NN) {
            int4 o;
            o.x = base;
            o.y = base + v.x;
            o.z = o.y + v.y;
            o.w = o.z + v.z;
            reinterpret_cast<int4*>(g_rowptr)[idx4] = o;
            reinterpret_cast<int4*>(g_count)[idx4] = o;   // same-thread rewrite
        }
        carry += blocktot;
        __syncthreads();
    }
}

// ---------------------------------------------------------------------------
// Bucket-place edges, 4 per thread (4 independent ATOMGs in flight).
// ---------------------------------------------------------------------------
__global__ __launch_bounds__(256) void build_kernel(const int* __restrict__ erow,
                                                    const int* __restrict__ ecol,
                                                    const float* __restrict__ eval_) {
    int t = blockIdx.x * 256 + threadIdx.x;
    if (t >= EE / 4) return;
    int4   r = reinterpret_cast<const int4*>(erow)[t];
    int4   c = reinterpret_cast<const int4*>(ecol)[t];
    float4 v = reinterpret_cast<const float4*>(eval_)[t];
    int p0 = atomicAdd(&g_count[r.x], 1);
    int p1 = atomicAdd(&g_count[r.y], 1);
    int p2 = atomicAdd(&g_count[r.z], 1);
    int p3 = atomicAdd(&g_count[r.w], 1);
    g_edge[p0] = make_int2(c.x, __float_as_int(v.x));
    g_edge[p1] = make_int2(c.y, __float_as_int(v.y));
    g_edge[p2] = make_int2(c.z, __float_as_int(v.z));
    g_edge[p3] = make_int2(c.w, __float_as_int(v.w));
}

// ---------------------------------------------------------------------------
// SpMM (r9 design, best measured): 4 lanes per row, warp = 8 rows.
// Lane gathers 48B fp16 per edge, 12 f32x2 accumulators, bias fused.
// Side job: re-zero g_count for the next call.
// ---------------------------------------------------------------------------
__global__ __launch_bounds__(256) void spmm_kernel(const float* __restrict__ b,
                                                   float* __restrict__ out) {
    {
        int zi = blockIdx.x * 256 + threadIdx.x;
        if (zi < NPAD) g_count[zi] = 0;     // grid 782*256 = 200192 covers NPAD
    }

    const int lane = threadIdx.x & 31;
    const int g    = lane >> 2;          // group 0..7
    const int sub  = lane & 3;           // 0..3
    const int row  = blockIdx.x * 64 + (threadIdx.x >> 5) * 8 + g;
    if (row >= NN) return;

    const int start = g_rowptr[row];
    const int end   = g_rowptr[row + 1];

    unsigned long long acc[12];
#pragma unroll
    for (int i = 0; i < 12; i++) acc[i] = 0ull;

    const uint4* s4 = reinterpret_cast<const uint4*>(g_support_h);  // 12 uint4/row

    for (int e = start; e < end; e++) {
        int2 ev = g_edge[e];                       // 4 lanes same addr: broadcast
        float vi = __int_as_float(ev.y);
        unsigned long long vv = pack2(vi, vi);
        size_t base = (size_t)ev.x * 12 + sub * 3;
        uint4 u0 = s4[base + 0];
        uint4 u1 = s4[base + 1];
        uint4 u2 = s4[base + 2];
        float2 f;
        f = __half22float2(*reinterpret_cast<const __half2*>(&u0.x)); fma2(acc[0],  pack2(f.x, f.y), vv);
        f = __half22float2(*reinterpret_cast<const __half2*>(&u0.y)); fma2(acc[1],  pack2(f.x, f.y), vv);
        f = __half22float2(*reinterpret_cast<const __half2*>(&u0.z)); fma2(acc[2],  pack2(f.x, f.y), vv);
        f = __half22float2(*reinterpret_cast<const __half2*>(&u0.w)); fma2(acc[3],  pack2(f.x, f.y), vv);
        f = __half22float2(*reinterpret_cast<const __half2*>(&u1.x)); fma2(acc[4],  pack2(f.x, f.y), vv);
        f = __half22float2(*reinterpret_cast<const __half2*>(&u1.y)); fma2(acc[5],  pack2(f.x, f.y), vv);
        f = __half22float2(*reinterpret_cast<const __half2*>(&u1.z)); fma2(acc[6],  pack2(f.x, f.y), vv);
        f = __half22float2(*reinterpret_cast<const __half2*>(&u1.w)); fma2(acc[7],  pack2(f.x, f.y), vv);
        f = __half22float2(*reinterpret_cast<const __half2*>(&u2.x)); fma2(acc[8],  pack2(f.x, f.y), vv);
        f = __half22float2(*reinterpret_cast<const __half2*>(&u2.y)); fma2(acc[9],  pack2(f.x, f.y), vv);
        f = __half22float2(*reinterpret_cast<const __half2*>(&u2.z)); fma2(acc[10], pack2(f.x, f.y), vv);
        f = __half22float2(*reinterpret_cast<const __half2*>(&u2.w)); fma2(acc[11], pack2(f.x, f.y), vv);
    }

    const float4* b4 = reinterpret_cast<const float4*>(b);
    float4* o4 = reinterpret_cast<float4*>(out) + (size_t)row * DD4 + sub * 6;
#pragma unroll
    for (int q = 0; q < 6; q++) {
        float4 bb = b4[sub * 6 + q];
        float4 r;
        r.x = __uint_as_float((unsigned)(acc[q * 2 + 0]))         + bb.x;
        r.y = __uint_as_float((unsigned)(acc[q * 2 + 0] >> 32))   + bb.y;
        r.z = __uint_as_float((unsigned)(acc[q * 2 + 1]))         + bb.z;
        r.w = __uint_as_float((unsigned)(acc[q * 2 + 1] >> 32))   + bb.w;
        o4[q] = r;
    }
}

// ---------------------------------------------------------------------------
// Launch: fork-join graph. Stream0: gemm.  Stream1: hist -> scan -> build.
// Join, then spmm on stream0.
// ---------------------------------------------------------------------------
extern "C" void kernel_launch(void* const* d_in, const int* in_sizes, int n_in,
                              void* d_out, int out_size) {
    const float* x     = (const float*)d_in[0];
    const int*   erow  = (const int*)d_in[1];
    const int*   ecol  = (const int*)d_in[2];
    const float* evalv = (const float*)d_in[3];
    const float* w     = (const float*)d_in[4];
    const float* b     = (const float*)d_in[5];
    float* out = (float*)d_out;

    static cudaStream_t s1 = nullptr;
    static cudaEvent_t evFork = nullptr, evJoin = nullptr;
    if (s1 == nullptr) {
        cudaStreamCreateWithFlags(&s1, cudaStreamNonBlocking);
        cudaEventCreateWithFlags(&evFork, cudaEventDisableTiming);
        cudaEventCreateWithFlags(&evJoin, cudaEventDisableTiming);
    }

    cudaStream_t s0 = 0;   // the stream kernel_launch is captured on

    // fork: s1 depends on everything upstream of this call
    cudaEventRecord(evFork, s0);
    cudaStreamWaitEvent(s1, evFork, 0);

    // branch A (s0): dense GEMM
    gemm_kernel<<<(NN + 31) / 32, 96, 0, s0>>>(x, w);

    // branch B (s1): counting sort of edges
    hist_kernel<<<(EE + 255) / 256, 256, 0, s1>>>(erow);
    scan_kernel<<<1, 1024, 0, s1>>>();
    build_kernel<<<(EE / 4 + 255) / 256, 256, 0, s1>>>(erow, ecol, evalv);

    // join
    cudaEventRecord(evJoin, s1);
    cudaStreamWaitEvent(s0, evJoin, 0);

    // consumer
    spmm_kernel<<<(NN + 63) / 64, 256, 0, s0>>>(b, out);
}

// round 15
// speedup vs baseline: 1.5342x; 1.0732x over previous
#include <cuda_runtime.h>
#include <cuda_bf16.h>
#include <cuda_fp16.h>
#include <cstdint>

#define NN 50000
#define EE 800000
#define DD 96
#define DD4 24
#define NPAD 53248          // 13 tiles * 4096, padded for int4 scan

// scratch (zero-initialized at load; g_count kept zeroed call-to-call by spmm)
__device__ __half g_support_h[(size_t)NN * DD];  // X @ W in fp16 (9.6 MB)
__device__ int   g_count[NPAD];                  // histogram (zeroed by spmm)
__device__ int   g_rowptr[NN + 1];
__device__ int   g_rank[EE];                     // edge rank within its row
__device__ int2  g_edge[EE];                     // sorted (col, val_bits)

// ---- f32x2 helpers -------------------------------------------------------
__device__ __forceinline__ void fma2(unsigned long long& d,
                                     unsigned long long a,
                                     unsigned long long b) {
    asm("fma.rn.f32x2 %0, %1, %2, %0;" : "+l"(d) : "l"(a), "l"(b));
}
__device__ __forceinline__ unsigned long long pack2(float lo, float hi) {
    unsigned long long r;
    asm("mov.b64 %0, {%1, %2};" : "=l"(r) : "f"(lo), "f"(hi));
    return r;
}
__device__ __forceinline__ unsigned h2u(__half2 h) {
    return *reinterpret_cast<unsigned*>(&h);
}

// ---------------------------------------------------------------------------
// GEMM: support[N,96] = X[N,96] @ W[96,96], f32x2 packed FMA, fp16 store.
// Tail: fused rank-histogram — rank[e] = atomicAdd(&count[row],1).
// Atomic latency drains in the shadow of other blocks' FMA work.
// ---------------------------------------------------------------------------
__global__ __launch_bounds__(96) void gemm_kernel(const float* __restrict__ x,
                                                  const float* __restrict__ w,
                                                  const int* __restrict__ erow) {
    __shared__ float Ws[DD * DD];      // [k][col]
    __shared__ float Xt[DD * 32];      // [k][row]

    const int tid = threadIdx.x;       // 0..95
    const int row0 = blockIdx.x * 32;

    {
        const float4* w4 = reinterpret_cast<const float4*>(w);
        float4* ws4 = reinterpret_cast<float4*>(Ws);
#pragma unroll
        for (int i = 0; i < 24; i++) ws4[tid + i * 96] = w4[tid + i * 96];
    }
    {
        const int r = tid & 31;
        const int wp = tid >> 5;
        const int gr = row0 + r;
        const float4* x4 = reinterpret_cast<const float4*>(x);
#pragma unroll
        for (int i = 0; i < 8; i++) {
            int k4 = wp + 3 * i;
            float4 v = make_float4(0.f, 0.f, 0.f, 0.f);
            if (gr < NN) v = x4[(size_t)gr * DD4 + k4];
            Xt[(k4 * 4 + 0) * 32 + r] = v.x;
            Xt[(k4 * 4 + 1) * 32 + r] = v.y;
            Xt[(k4 * 4 + 2) * 32 + r] = v.z;
            Xt[(k4 * 4 + 3) * 32 + r] = v.w;
        }
    }
    __syncthreads();

    const int rt = tid / DD4;
    const int ct = tid % DD4;

    unsigned long long acc[4][4];
#pragma unroll
    for (int i = 0; i < 4; i++)
#pragma unroll
        for (int j = 0; j < 4; j++) acc[i][j] = 0ull;

    const float4* ws4 = reinterpret_cast<const float4*>(Ws);
#pragma unroll 4
    for (int k = 0; k < DD; k++) {
        const double* xp = reinterpret_cast<const double*>(Xt + k * 32 + rt * 8);
        unsigned long long x0 = __double_as_longlong(xp[0]);
        unsigned long long x1 = __double_as_longlong(xp[1]);
        unsigned long long x2 = __double_as_longlong(xp[2]);
        unsigned long long x3 = __double_as_longlong(xp[3]);
        float4 wv = ws4[k * DD4 + ct];
        unsigned long long w0 = pack2(wv.x, wv.x);
        unsigned long long w1 = pack2(wv.y, wv.y);
        unsigned long long w2 = pack2(wv.z, wv.z);
        unsigned long long w3 = pack2(wv.w, wv.w);
        fma2(acc[0][0], x0, w0); fma2(acc[0][1], x0, w1); fma2(acc[0][2], x0, w2); fma2(acc[0][3], x0, w3);
        fma2(acc[1][0], x1, w0); fma2(acc[1][1], x1, w1); fma2(acc[1][2], x1, w2); fma2(acc[1][3], x1, w3);
        fma2(acc[2][0], x2, w0); fma2(acc[2][1], x2, w1); fma2(acc[2][2], x2, w2); fma2(acc[2][3], x2, w3);
        fma2(acc[3][0], x3, w0); fma2(acc[3][1], x3, w1); fma2(acc[3][2], x3, w2); fma2(acc[3][3], x3, w3);
    }

    uint2* s2 = reinterpret_cast<uint2*>(g_support_h);
#pragma unroll
    for (int i = 0; i < 4; i++) {
        int grl = row0 + rt * 8 + 2 * i;
        float l0 = __uint_as_float((unsigned)(acc[i][0]));
        float l1 = __uint_as_float((unsigned)(acc[i][1]));
        float l2 = __uint_as_float((unsigned)(acc[i][2]));
        float l3 = __uint_as_float((unsigned)(acc[i][3]));
        float h0 = __uint_as_float((unsigned)(acc[i][0] >> 32));
        float h1 = __uint_as_float((unsigned)(acc[i][1] >> 32));
        float h2 = __uint_as_float((unsigned)(acc[i][2] >> 32));
        float h3 = __uint_as_float((unsigned)(acc[i][3] >> 32));
        uint2 lo, hi;
        lo.x = h2u(__floats2half2_rn(l0, l1));
        lo.y = h2u(__floats2half2_rn(l2, l3));
        hi.x = h2u(__floats2half2_rn(h0, h1));
        hi.y = h2u(__floats2half2_rn(h2, h3));
        if (grl < NN)     s2[(size_t)grl * DD4 + ct] = lo;
        if (grl + 1 < NN) s2[(size_t)(grl + 1) * DD4 + ct] = hi;
    }

    // ---- fused rank-histogram tail ----
    {
        const int T = gridDim.x * 96;              // 150048
        for (int e = blockIdx.x * 96 + tid; e < EE; e += T)
            g_rank[e] = atomicAdd(&g_count[erow[e]], 1);
    }
}

// ---------------------------------------------------------------------------
// Single-block exclusive scan over g_count[0..NPAD) -> g_rowptr.
// ---------------------------------------------------------------------------
__global__ __launch_bounds__(1024) void scan_kernel() {
    __shared__ int warpsum[32];
    __shared__ int blocktot;

    const int t = threadIdx.x;
    const int lane = t & 31;
    const int wid = t >> 5;

    if (t == 0) g_rowptr[NN] = EE;

    int carry = 0;
    const int4* c4 = reinterpret_cast<const int4*>(g_count);

#pragma unroll
    for (int tile = 0; tile < 13; tile++) {
        int idx4 = tile * 1024 + t;
        int4 v = c4[idx4];
        int s = v.x + v.y + v.z + v.w;

        int inc = s;
#pragma unroll
        for (int off = 1; off < 32; off <<= 1) {
            int n = __shfl_up_sync(0xffffffffu, inc, off);
            if (lane >= off) inc += n;
        }
        if (lane == 31) warpsum[wid] = inc;
        __syncthreads();

        if (wid == 0) {
            int ws = warpsum[lane];
            int winc = ws;
#pragma unroll
            for (int off = 1; off < 32; off <<= 1) {
                int n = __shfl_up_sync(0xffffffffu, winc, off);
                if (lane >= off) winc += n;
            }
            warpsum[lane] = winc - ws;
            if (lane == 31) blocktot = winc;
        }
        __syncthreads();

        int base = carry + warpsum[wid] + (inc - s);
        int i0 = idx4 * 4;
        if (i0 < NN) {
            int4 o;
            o.x = base;
            o.y = base + v.x;
            o.z = o.y + v.y;
            o.w = o.z + v.z;
            reinterpret_cast<int4*>(g_rowptr)[idx4] = o;
        }
        carry += blocktot;
        __syncthreads();
    }
}

// ---------------------------------------------------------------------------
// Bucket-place edges, atomic-free: pos = rowptr[row] + rank[edge].
// 4 edges per thread, all-streaming loads, scattered STG.64.
// ---------------------------------------------------------------------------
__global__ __launch_bounds__(256) void build_kernel(const int* __restrict__ erow,
                                                    const int* __restrict__ ecol,
                                                    const float* __restrict__ eval_) {
    int t = blockIdx.x * 256 + threadIdx.x;
    if (t >= EE / 4) return;
    int4   r  = reinterpret_cast<const int4*>(erow)[t];
    int4   rk = reinterpret_cast<const int4*>(g_rank)[t];
    int4   c  = reinterpret_cast<const int4*>(ecol)[t];
    float4 v  = reinterpret_cast<const float4*>(eval_)[t];
    int p0 = g_rowptr[r.x] + rk.x;
    int p1 = g_rowptr[r.y] + rk.y;
    int p2 = g_rowptr[r.z] + rk.z;
    int p3 = g_rowptr[r.w] + rk.w;
    g_edge[p0] = make_int2(c.x, __float_as_int(v.x));
    g_edge[p1] = make_int2(c.y, __float_as_int(v.y));
    g_edge[p2] = make_int2(c.z, __float_as_int(v.z));
    g_edge[p3] = make_int2(c.w, __float_as_int(v.w));
}

// ---------------------------------------------------------------------------
// SpMM (r9 design, best measured): 4 lanes per row, warp = 8 rows.
// Lane gathers 48B fp16 per edge, 12 f32x2 accumulators, bias fused.
// Side job: re-zero g_count for the next call.
// ---------------------------------------------------------------------------
__global__ __launch_bounds__(256) void spmm_kernel(const float* __restrict__ b,
                                                   float* __restrict__ out) {
    {
        int zi = blockIdx.x * 256 + threadIdx.x;
        if (zi < NPAD) g_count[zi] = 0;     // grid 782*256 = 200192 covers NPAD
    }

    const int lane = threadIdx.x & 31;
    const int g    = lane >> 2;          // group 0..7
    const int sub  = lane & 3;           // 0..3
    const int row  = blockIdx.x * 64 + (threadIdx.x >> 5) * 8 + g;
    if (row >= NN) return;

    const int start = g_rowptr[row];
    const int end   = g_rowptr[row + 1];

    unsigned long long acc[12];
#pragma unroll
    for (int i = 0; i < 12; i++) acc[i] = 0ull;

    const uint4* s4 = reinterpret_cast<const uint4*>(g_support_h);  // 12 uint4/row

    for (int e = start; e < end; e++) {
        int2 ev = g_edge[e];                       // 4 lanes same addr: broadcast
        float vi = __int_as_float(ev.y);
        unsigned long long vv = pack2(vi, vi);
        size_t base = (size_t)ev.x * 12 + sub * 3;
        uint4 u0 = s4[base + 0];
        uint4 u1 = s4[base + 1];
        uint4 u2 = s4[base + 2];
        float2 f;
        f = __half22float2(*reinterpret_cast<const __half2*>(&u0.x)); fma2(acc[0],  pack2(f.x, f.y), vv);
        f = __half22float2(*reinterpret_cast<const __half2*>(&u0.y)); fma2(acc[1],  pack2(f.x, f.y), vv);
        f = __half22float2(*reinterpret_cast<const __half2*>(&u0.z)); fma2(acc[2],  pack2(f.x, f.y), vv);
        f = __half22float2(*reinterpret_cast<const __half2*>(&u0.w)); fma2(acc[3],  pack2(f.x, f.y), vv);
        f = __half22float2(*reinterpret_cast<const __half2*>(&u1.x)); fma2(acc[4],  pack2(f.x, f.y), vv);
        f = __half22float2(*reinterpret_cast<const __half2*>(&u1.y)); fma2(acc[5],  pack2(f.x, f.y), vv);
        f = __half22float2(*reinterpret_cast<const __half2*>(&u1.z)); fma2(acc[6],  pack2(f.x, f.y), vv);
        f = __half22float2(*reinterpret_cast<const __half2*>(&u1.w)); fma2(acc[7],  pack2(f.x, f.y), vv);
        f = __half22float2(*reinterpret_cast<const __half2*>(&u2.x)); fma2(acc[8],  pack2(f.x, f.y), vv);
        f = __half22float2(*reinterpret_cast<const __half2*>(&u2.y)); fma2(acc[9],  pack2(f.x, f.y), vv);
        f = __half22float2(*reinterpret_cast<const __half2*>(&u2.z)); fma2(acc[10], pack2(f.x, f.y), vv);
        f = __half22float2(*reinterpret_cast<const __half2*>(&u2.w)); fma2(acc[11], pack2(f.x, f.y), vv);
    }

    const float4* b4 = reinterpret_cast<const float4*>(b);
    float4* o4 = reinterpret_cast<float4*>(out) + (size_t)row * DD4 + sub * 6;
#pragma unroll
    for (int q = 0; q < 6; q++) {
        float4 bb = b4[sub * 6 + q];
        float4 r;
        r.x = __uint_as_float((unsigned)(acc[q * 2 + 0]))         + bb.x;
        r.y = __uint_as_float((unsigned)(acc[q * 2 + 0] >> 32))   + bb.y;
        r.z = __uint_as_float((unsigned)(acc[q * 2 + 1]))         + bb.z;
        r.w = __uint_as_float((unsigned)(acc[q * 2 + 1] >> 32))   + bb.w;
        o4[q] = r;
    }
}

extern "C" void kernel_launch(void* const* d_in, const int* in_sizes, int n_in,
                              void* d_out, int out_size) {
    const float* x     = (const float*)d_in[0];
    const int*   erow  = (const int*)d_in[1];
    const int*   ecol  = (const int*)d_in[2];
    const float* evalv = (const float*)d_in[3];
    const float* w     = (const float*)d_in[4];
    const float* b     = (const float*)d_in[5];
    float* out = (float*)d_out;

    gemm_kernel<<<(NN + 31) / 32, 96>>>(x, w, erow);       // + fused rank-hist
    scan_kernel<<<1, 1024>>>();
    build_kernel<<<(EE / 4 + 255) / 256, 256>>>(erow, ecol, evalv);
    spmm_kernel<<<(NN + 63) / 64, 256>>>(b, out);          // + re-zero counters
}